// round 15
// baseline (speedup 1.0000x reference)
#include <cuda_runtime.h>
#include <cuda_fp16.h>
#include <math.h>
#include <stdint.h>

#define BATCH 32
#define DEPTH 12
#define CDIM 768
#define NHEADS 12
#define HD 64
#define NTOK 197
#define NPATCH 196
#define GRD 14
#define PSZ 16
#define HIDDIM 3072
#define NCLS 1000
#define IMG 224
#define HALFW 3

// ---------------- scratch (device globals; no allocation allowed) -------------
__device__ __half g_xp16[BATCH * NPATCH * CDIM];
__device__ __half g_h16[BATCH * NTOK * CDIM];
__device__ __half g_o16[BATCH * NTOK * CDIM];
__device__ __half g_mlp16[BATCH * NTOK * HIDDIM];
__device__ __half g_qkv16[BATCH * NTOK * 3 * CDIM];
__device__ float g_t[BATCH * NTOK * CDIM];
__device__ float g_h[BATCH * NTOK * CDIM];
__device__ float g_cls[BATCH * CDIM];

// weights: (N,K) layout, fp16
#define W_PATCH_SZ (CDIM * 3 * PSZ * PSZ)
#define W_QKV_SZ   (DEPTH * CDIM * 3 * CDIM)
#define W_PROJ_SZ  (DEPTH * CDIM * CDIM)
#define W_MLP1_SZ  (DEPTH * CDIM * HIDDIM)
#define W_MLP2_SZ  (DEPTH * HIDDIM * CDIM)
#define OFF_PATCH 0
#define OFF_QKV   (OFF_PATCH + W_PATCH_SZ)
#define OFF_PROJ  (OFF_QKV + W_QKV_SZ)
#define OFF_MLP1  (OFF_PROJ + W_PROJ_SZ)
#define OFF_MLP2  (OFF_MLP1 + W_MLP1_SZ)
#define W_TOTAL   (OFF_MLP2 + W_MLP2_SZ)
__device__ __half g_w16[W_TOTAL];

// ---------------- helpers ------------------------------------------------------
__device__ __forceinline__ uint32_t smem_u32(const void* p) {
    uint32_t a;
    asm("{ .reg .u64 t; cvta.to.shared.u64 t, %1; cvt.u32.u64 %0, t; }"
        : "=r"(a) : "l"(p));
    return a;
}
__device__ __forceinline__ void cp16(uint32_t dst_smem, const void* src, int size) {
    asm volatile("cp.async.cg.shared.global [%0], [%1], 16, %2;\n"
                 :: "r"(dst_smem), "l"(src), "r"(size));
}
__device__ __forceinline__ void cp_commit() {
    asm volatile("cp.async.commit_group;\n");
}
template <int NWAIT>
__device__ __forceinline__ void cp_wait() {
    asm volatile("cp.async.wait_group %0;\n" :: "n"(NWAIT));
}

__device__ __forceinline__ void mma_f16(float* d, const uint32_t* a, const uint32_t* b) {
    asm volatile(
        "mma.sync.aligned.m16n8k16.row.col.f32.f16.f16.f32 "
        "{%0,%1,%2,%3}, {%4,%5,%6,%7}, {%8,%9}, {%0,%1,%2,%3};"
        : "+f"(d[0]), "+f"(d[1]), "+f"(d[2]), "+f"(d[3])
        : "r"(a[0]), "r"(a[1]), "r"(a[2]), "r"(a[3]), "r"(b[0]), "r"(b[1]));
}

__device__ __forceinline__ void ldsm_x4(uint32_t& r0, uint32_t& r1,
                                        uint32_t& r2, uint32_t& r3, uint32_t addr) {
    asm volatile("ldmatrix.sync.aligned.m8n8.x4.shared.b16 {%0,%1,%2,%3}, [%4];"
                 : "=r"(r0), "=r"(r1), "=r"(r2), "=r"(r3) : "r"(addr));
}

// ================= FP16 tensor-core GEMM, cp.async 3-stage + ldmatrix =========
// C(MxN) = A(MxK) @ Bw(N,K)^T, A/Bw fp16, accumulate fp32.
// Block 128x128, 8 warps (warp tile 64x32 = 4x4 m16n8k16 frags), K slab 32.
#define GM 128
#define GN 128
#define GKH 32
#define ROWB 80                 // padded smem row: 64B data + 16B pad
#define ROWH 40
#define TILEB (GM * ROWB)       // 10240
#define STAGEB (2 * TILEB)      // 20480
#define NST 3
#define GSMEM (NST * STAGEB)    // 61440

template <bool GELU, bool OUTH>
__global__ void __launch_bounds__(256, 2)
gemm_h(int M, int N, int K,
       const __half* __restrict__ A, const __half* __restrict__ Bw,
       const float* __restrict__ bias, const float* __restrict__ resid,
       void* __restrict__ Cout) {
    extern __shared__ char dsm[];
    const uint32_t sb = smem_u32(dsm);
    const int tid = threadIdx.x;
    const int lane = tid & 31;
    const int warp = tid >> 5;
    const int m0 = blockIdx.y * GM;
    const int n0 = blockIdx.x * GN;
    const int wm = (warp >> 2) * 64;
    const int wn = (warp & 3) * 32;
    const int r = lane >> 2;
    const int c = lane & 3;

    const int l8 = lane & 7;
    const int lq = lane >> 3;

    float acc[4][4][4];
#pragma unroll
    for (int mt = 0; mt < 4; mt++)
#pragma unroll
        for (int nt = 0; nt < 4; nt++)
#pragma unroll
            for (int i = 0; i < 4; i++) acc[mt][nt][i] = 0.f;

    const int iters = K / GKH;

    auto load_stage = [&](int s, int k0) {
        const uint32_t aB = sb + s * STAGEB;
        const uint32_t bB = aB + TILEB;
#pragma unroll
        for (int j = 0; j < 2; j++) {
            int ci = tid + j * 256;
            int row = ci >> 2, ch = ci & 3;
            int gm = m0 + row;
            cp16(aB + row * ROWB + ch * 16,
                 &A[(size_t)gm * K + k0 + ch * 8], (gm < M) ? 16 : 0);
            cp16(bB + row * ROWB + ch * 16,
                 &Bw[(size_t)(n0 + row) * K + k0 + ch * 8], 16);
        }
    };

    load_stage(0, 0);
    cp_commit();
    load_stage(1, GKH);
    cp_commit();

    int buf = 0;
    for (int it = 0; it < iters; ++it) {
        cp_wait<1>();
        __syncthreads();

        const uint32_t aS = sb + buf * STAGEB;
        const uint32_t bS = aS + TILEB;

#pragma unroll
        for (int ks = 0; ks < GKH; ks += 16) {
            uint32_t af[4][4], bf[4][2];
#pragma unroll
            for (int mt = 0; mt < 4; mt++) {
                int arow = wm + mt * 16 + l8 + ((lq & 1) << 3);
                int acolb = (ks + ((lq >> 1) << 3)) * 2;
                ldsm_x4(af[mt][0], af[mt][1], af[mt][2], af[mt][3],
                        aS + arow * ROWB + acolb);
            }
            {
                int brow = wn + ((lq >> 1) << 3) + l8;
                int bcolb = (ks + ((lq & 1) << 3)) * 2;
                ldsm_x4(bf[0][0], bf[0][1], bf[1][0], bf[1][1],
                        bS + brow * ROWB + bcolb);
                ldsm_x4(bf[2][0], bf[2][1], bf[3][0], bf[3][1],
                        bS + (brow + 16) * ROWB + bcolb);
            }
#pragma unroll
            for (int mt = 0; mt < 4; mt++)
#pragma unroll
                for (int nt = 0; nt < 4; nt++)
                    mma_f16(acc[mt][nt], af[mt], bf[nt]);
        }
        __syncthreads();

        if (it + 2 < iters) {
            int nb2 = buf + 2;
            if (nb2 >= NST) nb2 -= NST;
            load_stage(nb2, (it + 2) * GKH);
        }
        cp_commit();

        buf = (buf == NST - 1) ? 0 : buf + 1;
    }

    // ---- epilogue ----
#pragma unroll
    for (int mt = 0; mt < 4; mt++) {
#pragma unroll
        for (int half = 0; half < 2; half++) {
            int gm = m0 + wm + mt * 16 + r + half * 8;
            if (gm >= M) continue;
#pragma unroll
            for (int nt = 0; nt < 4; nt++) {
                int gn = n0 + wn + nt * 8 + c * 2;
                float v0 = acc[mt][nt][half * 2 + 0];
                float v1 = acc[mt][nt][half * 2 + 1];
                if (bias) {
                    v0 += bias[gn];
                    v1 += bias[gn + 1];
                }
                if (GELU) {
                    v0 = 0.5f * v0 * (1.f + erff(v0 * 0.70710678118654752f));
                    v1 = 0.5f * v1 * (1.f + erff(v1 * 0.70710678118654752f));
                }
                if (resid) {
                    const float2 rr = *reinterpret_cast<const float2*>(
                        &resid[(size_t)gm * N + gn]);
                    v0 += rr.x;
                    v1 += rr.y;
                }
                if (OUTH) {
                    __half2 hv = __floats2half2_rn(v0, v1);
                    *reinterpret_cast<__half2*>(
                        (__half*)Cout + (size_t)gm * N + gn) = hv;
                } else {
                    *reinterpret_cast<float2*>(
                        (float*)Cout + (size_t)gm * N + gn) = make_float2(v0, v1);
                }
            }
        }
    }
}

// ---------------- weight preprocessing ----------------------------------------
__global__ void half_kernel(const float* __restrict__ src, __half* __restrict__ dst,
                            int n4) {
    int i = blockIdx.x * blockDim.x + threadIdx.x;
    if (i >= n4) return;
    float4 v = reinterpret_cast<const float4*>(src)[i];
    __half2 h0 = __floats2half2_rn(v.x, v.y);
    __half2 h1 = __floats2half2_rn(v.z, v.w);
    reinterpret_cast<__half2*>(dst)[2 * i + 0] = h0;
    reinterpret_cast<__half2*>(dst)[2 * i + 1] = h1;
}

// (K,N) fp32 row-major -> (N,K) fp16 row-major; layer via blockIdx.z
__global__ void __launch_bounds__(256)
transpose_half_kernel(const float* __restrict__ src, __half* __restrict__ dst,
                      int K, int N) {
    __shared__ float tile[32][33];
    const float* s = src + (size_t)blockIdx.z * K * N;
    __half* d = dst + (size_t)blockIdx.z * K * N;
    int kb = blockIdx.y * 32, nb = blockIdx.x * 32;
    int tx = threadIdx.x & 31, ty = threadIdx.x >> 5;
#pragma unroll
    for (int r = 0; r < 32; r += 8)
        tile[ty + r][tx] = s[(size_t)(kb + ty + r) * N + nb + tx];
    __syncthreads();
#pragma unroll
    for (int r = 0; r < 32; r += 8)
        d[(size_t)(nb + ty + r) * K + kb + tx] = __float2half(tile[tx][ty + r]);
}

// ---------------- small SIMT GEMM (head: M=32, N=1000) ------------------------
#define BN 128

__global__ void __launch_bounds__(256)
gemm_small(int M, int N, int K,
           const float* __restrict__ A, const float* __restrict__ B,
           const float* __restrict__ bias, float* __restrict__ C) {
    __shared__ float As[8][128];
    __shared__ float Bs[8][132];
    const int tid = threadIdx.x;
    const int m0 = blockIdx.y * 128;
    const int n0 = blockIdx.x * BN;
    const int tx = tid % 16;
    const int ty = tid / 16;

    float acc[8][8];
#pragma unroll
    for (int i = 0; i < 8; i++)
#pragma unroll
        for (int j = 0; j < 8; j++) acc[i][j] = 0.f;

    const int arow = tid / 2;
    const int acol = (tid % 2) * 4;
    const int brow = tid / 32;
    const int bcol = (tid % 32) * 4;

    for (int k0 = 0; k0 < K; k0 += 8) {
        {
            int gm = m0 + arow;
            float4 v = make_float4(0.f, 0.f, 0.f, 0.f);
            if (gm < M)
                v = *reinterpret_cast<const float4*>(&A[(size_t)gm * K + k0 + acol]);
            As[acol + 0][arow] = v.x;
            As[acol + 1][arow] = v.y;
            As[acol + 2][arow] = v.z;
            As[acol + 3][arow] = v.w;
        }
        {
            int gn = n0 + bcol;
            Bs[brow][bcol + 0] = (gn + 0 < N) ? B[(size_t)(k0 + brow) * N + gn + 0] : 0.f;
            Bs[brow][bcol + 1] = (gn + 1 < N) ? B[(size_t)(k0 + brow) * N + gn + 1] : 0.f;
            Bs[brow][bcol + 2] = (gn + 2 < N) ? B[(size_t)(k0 + brow) * N + gn + 2] : 0.f;
            Bs[brow][bcol + 3] = (gn + 3 < N) ? B[(size_t)(k0 + brow) * N + gn + 3] : 0.f;
        }
        __syncthreads();
#pragma unroll
        for (int kk = 0; kk < 8; kk++) {
            float ra[8], rb[8];
#pragma unroll
            for (int i = 0; i < 8; i++) ra[i] = As[kk][ty * 8 + i];
#pragma unroll
            for (int j = 0; j < 8; j++) rb[j] = Bs[kk][tx * 8 + j];
#pragma unroll
            for (int i = 0; i < 8; i++)
#pragma unroll
                for (int j = 0; j < 8; j++) acc[i][j] = fmaf(ra[i], rb[j], acc[i][j]);
        }
        __syncthreads();
    }
#pragma unroll
    for (int i = 0; i < 8; i++) {
        int gm = m0 + ty * 8 + i;
        if (gm >= M) continue;
#pragma unroll
        for (int j = 0; j < 8; j++) {
            int gn = n0 + tx * 8 + j;
            if (gn >= N) continue;
            float v = acc[i][j];
            if (bias) v += bias[gn];
            C[(size_t)gm * N + gn] = v;
        }
    }
}

// ---------------- patch gather (fp16 output) ----------------------------------
__global__ void gather_kernel(const float* __restrict__ x) {
    int idx = blockIdx.x * blockDim.x + threadIdx.x;
    const int total = BATCH * NPATCH * CDIM;
    if (idx >= total) return;
    int k = idx % CDIM;
    int g = (idx / CDIM) % NPATCH;
    int b = idx / (CDIM * NPATCH);
    int ch = k / (PSZ * PSZ);
    int pr = (k / PSZ) % PSZ;
    int pc = k % PSZ;
    int gr = g / GRD;
    int gc = g % GRD;
    g_xp16[idx] = __float2half(
        x[(((size_t)b * 3 + ch) * IMG + gr * PSZ + pr) * IMG + gc * PSZ + pc]);
}

// ---------------- assemble t = [cls; patches] + pos --------------------------
__global__ void assemble_kernel(const float* __restrict__ cls_tok,
                                const float* __restrict__ pos) {
    int idx = blockIdx.x * blockDim.x + threadIdx.x;
    const int total = BATCH * NTOK * CDIM;
    if (idx >= total) return;
    int c = idx % CDIM;
    int n = (idx / CDIM) % NTOK;
    int b = idx / (CDIM * NTOK);
    float v = (n == 0) ? cls_tok[c] : g_h[((size_t)b * NPATCH + n - 1) * CDIM + c];
    g_t[idx] = v + pos[(size_t)n * CDIM + c];
}

// ---------------- layernorm (warp-shuffle; half or float out) -----------------
__global__ void __launch_bounds__(256)
ln_kernel(const float* __restrict__ x, long in_stride,
          const float* __restrict__ w, const float* __restrict__ b,
          void* __restrict__ y, long out_stride, int half_out) {
    const float* row = x + (size_t)blockIdx.x * in_stride;
    int tid = threadIdx.x;
    float v0 = row[tid], v1 = row[tid + 256], v2 = row[tid + 512];
    float s = v0 + v1 + v2;
    float s2 = v0 * v0 + v1 * v1 + v2 * v2;
#pragma unroll
    for (int o = 16; o > 0; o >>= 1) {
        s += __shfl_xor_sync(0xffffffffu, s, o);
        s2 += __shfl_xor_sync(0xffffffffu, s2, o);
    }
    __shared__ float ps[8], ps2[8];
    if ((tid & 31) == 0) {
        ps[tid >> 5] = s;
        ps2[tid >> 5] = s2;
    }
    __syncthreads();
    float ts = ps[tid & 7], ts2 = ps2[tid & 7];
#pragma unroll
    for (int o = 4; o > 0; o >>= 1) {
        ts += __shfl_xor_sync(0xffffffffu, ts, o);
        ts2 += __shfl_xor_sync(0xffffffffu, ts2, o);
    }
    float mu = ts * (1.f / CDIM);
    float var = ts2 * (1.f / CDIM) - mu * mu;
    float rstd = rsqrtf(var + 1e-5f);
    float o0 = (v0 - mu) * rstd * w[tid] + b[tid];
    float o1 = (v1 - mu) * rstd * w[tid + 256] + b[tid + 256];
    float o2 = (v2 - mu) * rstd * w[tid + 512] + b[tid + 512];
    if (half_out) {
        __half* out = (__half*)y + (size_t)blockIdx.x * out_stride;
        out[tid] = __float2half(o0);
        out[tid + 256] = __float2half(o1);
        out[tid + 512] = __float2half(o2);
    } else {
        float* out = (float*)y + (size_t)blockIdx.x * out_stride;
        out[tid] = o0;
        out[tid + 256] = o1;
        out[tid + 512] = o2;
    }
}

// ---------------- fused flash attention (fp16 qkv in, float4 smem) ------------
#define FBQ 32
#define FBK 32
#define FPAD 4

__device__ __forceinline__ bool attn_allowed(int q, int k) {
    if (q == 0 || k == 0) return true;
    int qr = (q - 1) / GRD, qc = (q - 1) % GRD;
    int kr = (k - 1) / GRD, kc = (k - 1) % GRD;
    return (abs(qr - kr) <= HALFW) && (abs(qc - kc) <= HALFW);
}

__device__ __forceinline__ void h8_to_smem(const uint4& raw, float* dst) {
    const __half2* hp = reinterpret_cast<const __half2*>(&raw);
    float2 f0 = __half22float2(hp[0]);
    float2 f1 = __half22float2(hp[1]);
    float2 f2 = __half22float2(hp[2]);
    float2 f3 = __half22float2(hp[3]);
    *reinterpret_cast<float4*>(dst) = make_float4(f0.x, f0.y, f1.x, f1.y);
    *reinterpret_cast<float4*>(dst + 4) = make_float4(f2.x, f2.y, f3.x, f3.y);
}

__global__ void __launch_bounds__(256)
flash_kernel() {
    const int b = blockIdx.z;
    const int h = blockIdx.y;
    const int q0 = blockIdx.x * FBQ;
    const int tid = threadIdx.x;

    __shared__ float Qs[FBQ][HD + FPAD];
    __shared__ float Ks[FBK][HD + FPAD];
    __shared__ float Vs[FBK][HD + FPAD];
    __shared__ float Ps[FBQ][FBK + 1];

    const __half* qkv = g_qkv16;
    const size_t rowstride = 3 * CDIM;

    // load Q tile: 8 halves (16B) per thread-iter
    {
        int idx = tid;  // FBQ * HD/8 = 256 exactly
        int q = idx >> 3, d8 = (idx & 7) * 8;
        int gq = q0 + q;
        uint4 raw = make_uint4(0u, 0u, 0u, 0u);
        if (gq < NTOK)
            raw = *reinterpret_cast<const uint4*>(
                &qkv[((size_t)(b * NTOK + gq)) * rowstride + h * HD + d8]);
        h8_to_smem(raw, &Qs[q][d8]);
    }

    int klo = 0, khi = NTOK - 1;
    bool full = (q0 == 0);
    if (!full) {
        int qlo = q0, qhi = min(q0 + FBQ - 1, NTOK - 1);
        int qr_min = (qlo - 1) / GRD, qr_max = (qhi - 1) / GRD;
        klo = 1 + max(0, qr_min - HALFW) * GRD;
        khi = min(NTOK - 1, (qr_max + HALFW) * GRD + GRD);
    }

    const int q = tid >> 3;
    const int j = tid & 7;
    const int gq = q0 + q;
    const bool qvalid = (gq < NTOK);
    const int dbase = j * 8;

    float m_old = -INFINITY, l = 0.f;
    float acc[8];
#pragma unroll
    for (int i = 0; i < 8; i++) acc[i] = 0.f;

    for (int kt = 0; kt < (NTOK + FBK - 1) / FBK; kt++) {
        int kbase = kt * FBK;
        if (!(kt == 0 || full || (kbase + FBK - 1 >= klo && kbase <= khi)))
            continue;

        __syncthreads();
        // load K,V tiles (8 halves per load)
        {
            int idx = tid;  // FBK * HD/8 = 256 exactly
            int kk = idx >> 3, d8 = (idx & 7) * 8;
            int gk = kbase + kk;
            uint4 kraw = make_uint4(0u, 0u, 0u, 0u);
            uint4 vraw = make_uint4(0u, 0u, 0u, 0u);
            if (gk < NTOK) {
                kraw = *reinterpret_cast<const uint4*>(
                    &qkv[((size_t)(b * NTOK + gk)) * rowstride + CDIM + h * HD + d8]);
                vraw = *reinterpret_cast<const uint4*>(
                    &qkv[((size_t)(b * NTOK + gk)) * rowstride + 2 * CDIM + h * HD + d8]);
            }
            h8_to_smem(kraw, &Ks[kk][d8]);
            h8_to_smem(vraw, &Vs[kk][d8]);
        }
        __syncthreads();

        // scores: 4 key columns kc = j + 8*i, float4 dot
        float s[4] = {0.f, 0.f, 0.f, 0.f};
#pragma unroll
        for (int d4 = 0; d4 < HD; d4 += 4) {
            float4 qv = *reinterpret_cast<const float4*>(&Qs[q][d4]);
#pragma unroll
            for (int i = 0; i < 4; i++) {
                float4 kv = *reinterpret_cast<const float4*>(&Ks[j + i * 8][d4]);
                s[i] = fmaf(qv.x, kv.x, s[i]);
                s[i] = fmaf(qv.y, kv.y, s[i]);
                s[i] = fmaf(qv.z, kv.z, s[i]);
                s[i] = fmaf(qv.w, kv.w, s[i]);
            }
        }
#pragma unroll
        for (int i = 0; i < 4; i++) {
            float a = s[i] * 0.125f;
            int gk = kbase + j + i * 8;
            if (!qvalid || gk >= NTOK || !attn_allowed(gq, gk)) a = -INFINITY;
            s[i] = a;
        }
        float mt = fmaxf(fmaxf(s[0], s[1]), fmaxf(s[2], s[3]));
#pragma unroll
        for (int o = 1; o < 8; o <<= 1)
            mt = fmaxf(mt, __shfl_xor_sync(0xffffffffu, mt, o));
        float m_new = fmaxf(m_old, mt);
        float scale = (m_new == -INFINITY) ? 1.f : __expf(m_old - m_new);
        float psum = 0.f;
#pragma unroll
        for (int i = 0; i < 4; i++) {
            float p = (s[i] == -INFINITY) ? 0.f : __expf(s[i] - m_new);
            Ps[q][j + i * 8] = p;
            psum += p;
        }
#pragma unroll
        for (int o = 1; o < 8; o <<= 1)
            psum += __shfl_xor_sync(0xffffffffu, psum, o);
        l = l * scale + psum;
        m_old = m_new;
        __syncwarp();

        // PV accumulate (float4 V loads)
#pragma unroll
        for (int i = 0; i < 8; i++) acc[i] *= scale;
        for (int kk = 0; kk < FBK; kk++) {
            float p = Ps[q][kk];
            float4 v0 = *reinterpret_cast<const float4*>(&Vs[kk][dbase]);
            float4 v1 = *reinterpret_cast<const float4*>(&Vs[kk][dbase + 4]);
            acc[0] = fmaf(p, v0.x, acc[0]);
            acc[1] = fmaf(p, v0.y, acc[1]);
            acc[2] = fmaf(p, v0.z, acc[2]);
            acc[3] = fmaf(p, v0.w, acc[3]);
            acc[4] = fmaf(p, v1.x, acc[4]);
            acc[5] = fmaf(p, v1.y, acc[5]);
            acc[6] = fmaf(p, v1.z, acc[6]);
            acc[7] = fmaf(p, v1.w, acc[7]);
        }
        __syncwarp();
    }

    if (qvalid) {
        float inv = 1.f / l;
        __half2 hv[4];
#pragma unroll
        for (int i = 0; i < 4; i++)
            hv[i] = __floats2half2_rn(acc[2 * i] * inv, acc[2 * i + 1] * inv);
        *reinterpret_cast<uint2*>(
            &g_o16[((size_t)(b * NTOK + gq)) * CDIM + h * HD + dbase]) =
            *reinterpret_cast<uint2*>(&hv[0]);
        *reinterpret_cast<uint2*>(
            &g_o16[((size_t)(b * NTOK + gq)) * CDIM + h * HD + dbase + 4]) =
            *reinterpret_cast<uint2*>(&hv[2]);
    }
}

// ---------------- launch helpers ---------------------------------------------
static inline dim3 gh_grid(int M, int N) {
    return dim3(N / GN, (M + GM - 1) / GM);
}

extern "C" void kernel_launch(void* const* d_in, const int* in_sizes, int n_in,
                              void* d_out, int out_size) {
    const float* x       = (const float*)d_in[0];
    const float* patch_w = (const float*)d_in[1];
    const float* patch_b = (const float*)d_in[2];
    const float* cls_tok = (const float*)d_in[3];
    const float* pos     = (const float*)d_in[4];
    const float* ln1_w   = (const float*)d_in[5];
    const float* ln1_b   = (const float*)d_in[6];
    const float* qkv_w   = (const float*)d_in[7];
    const float* proj_w  = (const float*)d_in[8];
    const float* proj_b  = (const float*)d_in[9];
    const float* ln2_w   = (const float*)d_in[10];
    const float* ln2_b   = (const float*)d_in[11];
    const float* mlp_w1  = (const float*)d_in[12];
    const float* mlp_b1  = (const float*)d_in[13];
    const float* mlp_w2  = (const float*)d_in[14];
    const float* mlp_b2  = (const float*)d_in[15];
    const float* norm_w  = (const float*)d_in[16];
    const float* norm_b  = (const float*)d_in[17];
    const float* head_w  = (const float*)d_in[18];
    const float* head_b  = (const float*)d_in[19];
    float* out = (float*)d_out;

    float *t, *h, *cls;
    __half *xp16, *h16, *o16, *mlp16, *qkv16, *w16;
    cudaGetSymbolAddress((void**)&t, g_t);
    cudaGetSymbolAddress((void**)&h, g_h);
    cudaGetSymbolAddress((void**)&cls, g_cls);
    cudaGetSymbolAddress((void**)&xp16, g_xp16);
    cudaGetSymbolAddress((void**)&h16, g_h16);
    cudaGetSymbolAddress((void**)&o16, g_o16);
    cudaGetSymbolAddress((void**)&mlp16, g_mlp16);
    cudaGetSymbolAddress((void**)&qkv16, g_qkv16);
    cudaGetSymbolAddress((void**)&w16, g_w16);

    cudaFuncSetAttribute(gemm_h<false, false>,
                         cudaFuncAttributeMaxDynamicSharedMemorySize, GSMEM);
    cudaFuncSetAttribute(gemm_h<false, true>,
                         cudaFuncAttributeMaxDynamicSharedMemorySize, GSMEM);
    cudaFuncSetAttribute(gemm_h<true, true>,
                         cudaFuncAttributeMaxDynamicSharedMemorySize, GSMEM);

    const __half* w_patch = w16 + OFF_PATCH;
    const __half* w_qkv   = w16 + OFF_QKV;
    const __half* w_proj  = w16 + OFF_PROJ;
    const __half* w_mlp1  = w16 + OFF_MLP1;
    const __half* w_mlp2  = w16 + OFF_MLP2;

    // ---- preprocess weights: (N,K) fp16 ----
    half_kernel<<<(W_PATCH_SZ / 4 + 255) / 256, 256>>>(
        patch_w, w16 + OFF_PATCH, W_PATCH_SZ / 4);  // already (N,K)
    transpose_half_kernel<<<dim3(3 * CDIM / 32, CDIM / 32, DEPTH), 256>>>(
        qkv_w, w16 + OFF_QKV, CDIM, 3 * CDIM);
    transpose_half_kernel<<<dim3(CDIM / 32, CDIM / 32, DEPTH), 256>>>(
        proj_w, w16 + OFF_PROJ, CDIM, CDIM);
    transpose_half_kernel<<<dim3(HIDDIM / 32, CDIM / 32, DEPTH), 256>>>(
        mlp_w1, w16 + OFF_MLP1, CDIM, HIDDIM);
    transpose_half_kernel<<<dim3(CDIM / 32, HIDDIM / 32, DEPTH), 256>>>(
        mlp_w2, w16 + OFF_MLP2, HIDDIM, CDIM);

    const int Mtok = BATCH * NTOK;  // 6304

    // patch embed
    {
        int total = BATCH * NPATCH * CDIM;
        gather_kernel<<<(total + 255) / 256, 256>>>(x);
        gemm_h<false, false><<<gh_grid(BATCH * NPATCH, CDIM), 256, GSMEM>>>(
            BATCH * NPATCH, CDIM, CDIM, xp16, w_patch, patch_b, nullptr, h);
        int tot2 = BATCH * NTOK * CDIM;
        assemble_kernel<<<(tot2 + 255) / 256, 256>>>(cls_tok, pos);
    }

    for (int i = 0; i < DEPTH; i++) {
        ln_kernel<<<Mtok, 256>>>(t, CDIM, ln1_w + i * CDIM, ln1_b + i * CDIM,
                                 h16, CDIM, 1);
        gemm_h<false, true><<<gh_grid(Mtok, 3 * CDIM), 256, GSMEM>>>(
            Mtok, 3 * CDIM, CDIM, h16, w_qkv + (size_t)i * CDIM * 3 * CDIM,
            nullptr, nullptr, qkv16);
        flash_kernel<<<dim3((NTOK + FBQ - 1) / FBQ, NHEADS, BATCH), 256>>>();
        gemm_h<false, false><<<gh_grid(Mtok, CDIM), 256, GSMEM>>>(
            Mtok, CDIM, CDIM, o16, w_proj + (size_t)i * CDIM * CDIM,
            proj_b + i * CDIM, t, t);
        ln_kernel<<<Mtok, 256>>>(t, CDIM, ln2_w + i * CDIM, ln2_b + i * CDIM,
                                 h16, CDIM, 1);
        gemm_h<true, true><<<gh_grid(Mtok, HIDDIM), 256, GSMEM>>>(
            Mtok, HIDDIM, CDIM, h16, w_mlp1 + (size_t)i * CDIM * HIDDIM,
            mlp_b1 + i * HIDDIM, nullptr, mlp16);
        gemm_h<false, false><<<gh_grid(Mtok, CDIM), 256, GSMEM>>>(
            Mtok, CDIM, HIDDIM, mlp16, w_mlp2 + (size_t)i * HIDDIM * CDIM,
            mlp_b2 + i * CDIM, t, t);
    }

    ln_kernel<<<BATCH, 256>>>(t, (long)NTOK * CDIM, norm_w, norm_b, cls, CDIM, 0);
    gemm_small<<<dim3((NCLS + BN - 1) / BN, 1), 256>>>(
        BATCH, NCLS, CDIM, cls, head_w, head_b, out);
}

// round 16
// speedup vs baseline: 1.0263x; 1.0263x over previous
#include <cuda_runtime.h>
#include <cuda_fp16.h>
#include <math.h>
#include <stdint.h>

#define BATCH 32
#define DEPTH 12
#define CDIM 768
#define NHEADS 12
#define HD 64
#define NTOK 197
#define NPATCH 196
#define GRD 14
#define PSZ 16
#define HIDDIM 3072
#define NCLS 1000
#define IMG 224
#define HALFW 3

// ---------------- scratch (device globals; no allocation allowed) -------------
__device__ __half g_xp16[BATCH * NPATCH * CDIM];
__device__ __half g_h16[BATCH * NTOK * CDIM];
__device__ __half g_o16[BATCH * NTOK * CDIM];
__device__ __half g_mlp16[BATCH * NTOK * HIDDIM];
__device__ __half g_qkv16[BATCH * NTOK * 3 * CDIM];
__device__ float g_t[BATCH * NTOK * CDIM];
__device__ float g_h[BATCH * NTOK * CDIM];
__device__ float g_cls[BATCH * CDIM];

// weights: (N,K) layout, fp16
#define W_PATCH_SZ (CDIM * 3 * PSZ * PSZ)
#define W_QKV_SZ   (DEPTH * CDIM * 3 * CDIM)
#define W_PROJ_SZ  (DEPTH * CDIM * CDIM)
#define W_MLP1_SZ  (DEPTH * CDIM * HIDDIM)
#define W_MLP2_SZ  (DEPTH * HIDDIM * CDIM)
#define OFF_PATCH 0
#define OFF_QKV   (OFF_PATCH + W_PATCH_SZ)
#define OFF_PROJ  (OFF_QKV + W_QKV_SZ)
#define OFF_MLP1  (OFF_PROJ + W_PROJ_SZ)
#define OFF_MLP2  (OFF_MLP1 + W_MLP1_SZ)
#define W_TOTAL   (OFF_MLP2 + W_MLP2_SZ)
__device__ __half g_w16[W_TOTAL];

// ---------------- helpers ------------------------------------------------------
__device__ __forceinline__ uint32_t smem_u32(const void* p) {
    uint32_t a;
    asm("{ .reg .u64 t; cvta.to.shared.u64 t, %1; cvt.u32.u64 %0, t; }"
        : "=r"(a) : "l"(p));
    return a;
}
__device__ __forceinline__ void cp16(uint32_t dst_smem, const void* src, int size) {
    asm volatile("cp.async.cg.shared.global [%0], [%1], 16, %2;\n"
                 :: "r"(dst_smem), "l"(src), "r"(size));
}
__device__ __forceinline__ void cp_commit() {
    asm volatile("cp.async.commit_group;\n");
}
template <int NWAIT>
__device__ __forceinline__ void cp_wait() {
    asm volatile("cp.async.wait_group %0;\n" :: "n"(NWAIT));
}

__device__ __forceinline__ void mma_f16(float* d, const uint32_t* a, const uint32_t* b) {
    asm volatile(
        "mma.sync.aligned.m16n8k16.row.col.f32.f16.f16.f32 "
        "{%0,%1,%2,%3}, {%4,%5,%6,%7}, {%8,%9}, {%0,%1,%2,%3};"
        : "+f"(d[0]), "+f"(d[1]), "+f"(d[2]), "+f"(d[3])
        : "r"(a[0]), "r"(a[1]), "r"(a[2]), "r"(a[3]), "r"(b[0]), "r"(b[1]));
}

__device__ __forceinline__ void ldsm_x4(uint32_t& r0, uint32_t& r1,
                                        uint32_t& r2, uint32_t& r3, uint32_t addr) {
    asm volatile("ldmatrix.sync.aligned.m8n8.x4.shared.b16 {%0,%1,%2,%3}, [%4];"
                 : "=r"(r0), "=r"(r1), "=r"(r2), "=r"(r3) : "r"(addr));
}

// ================= FP16 tensor-core GEMM, cp.async 3-stage + ldmatrix =========
// C(MxN) = A(MxK) @ Bw(N,K)^T, A/Bw fp16, accumulate fp32.
// Block 128x128, 8 warps (warp tile 64x32 = 4x4 m16n8k16 frags), K slab 32.
// Single barrier per K-iter: with NST=3, the refill target (buf+2 == buf-1 mod 3)
// was last read in iter it-1, and the barrier after cp_wait already orders that.
#define GM 128
#define GN 128
#define GKH 32
#define ROWB 80                 // padded smem row: 64B data + 16B pad
#define ROWH 40
#define TILEB (GM * ROWB)       // 10240
#define STAGEB (2 * TILEB)      // 20480
#define NST 3
#define GSMEM (NST * STAGEB)    // 61440

template <bool GELU, bool OUTH>
__global__ void __launch_bounds__(256, 2)
gemm_h(int M, int N, int K,
       const __half* __restrict__ A, const __half* __restrict__ Bw,
       const float* __restrict__ bias, const float* __restrict__ resid,
       void* __restrict__ Cout) {
    extern __shared__ char dsm[];
    const uint32_t sb = smem_u32(dsm);
    const int tid = threadIdx.x;
    const int lane = tid & 31;
    const int warp = tid >> 5;
    const int m0 = blockIdx.y * GM;
    const int n0 = blockIdx.x * GN;
    const int wm = (warp >> 2) * 64;
    const int wn = (warp & 3) * 32;
    const int r = lane >> 2;
    const int c = lane & 3;

    const int l8 = lane & 7;
    const int lq = lane >> 3;

    float acc[4][4][4];
#pragma unroll
    for (int mt = 0; mt < 4; mt++)
#pragma unroll
        for (int nt = 0; nt < 4; nt++)
#pragma unroll
            for (int i = 0; i < 4; i++) acc[mt][nt][i] = 0.f;

    const int iters = K / GKH;

    auto load_stage = [&](int s, int k0) {
        const uint32_t aB = sb + s * STAGEB;
        const uint32_t bB = aB + TILEB;
#pragma unroll
        for (int j = 0; j < 2; j++) {
            int ci = tid + j * 256;
            int row = ci >> 2, ch = ci & 3;
            int gm = m0 + row;
            cp16(aB + row * ROWB + ch * 16,
                 &A[(size_t)gm * K + k0 + ch * 8], (gm < M) ? 16 : 0);
            cp16(bB + row * ROWB + ch * 16,
                 &Bw[(size_t)(n0 + row) * K + k0 + ch * 8], 16);
        }
    };

    load_stage(0, 0);
    cp_commit();
    load_stage(1, GKH);
    cp_commit();

    int buf = 0;
    for (int it = 0; it < iters; ++it) {
        cp_wait<1>();
        __syncthreads();

        // prefetch for it+2 FIRST (overlaps with the mma loop below)
        if (it + 2 < iters) {
            int nb2 = buf + 2;
            if (nb2 >= NST) nb2 -= NST;
            load_stage(nb2, (it + 2) * GKH);
        }
        cp_commit();

        const uint32_t aS = sb + buf * STAGEB;
        const uint32_t bS = aS + TILEB;

#pragma unroll
        for (int ks = 0; ks < GKH; ks += 16) {
            uint32_t af[4][4], bf[4][2];
#pragma unroll
            for (int mt = 0; mt < 4; mt++) {
                int arow = wm + mt * 16 + l8 + ((lq & 1) << 3);
                int acolb = (ks + ((lq >> 1) << 3)) * 2;
                ldsm_x4(af[mt][0], af[mt][1], af[mt][2], af[mt][3],
                        aS + arow * ROWB + acolb);
            }
            {
                int brow = wn + ((lq >> 1) << 3) + l8;
                int bcolb = (ks + ((lq & 1) << 3)) * 2;
                ldsm_x4(bf[0][0], bf[0][1], bf[1][0], bf[1][1],
                        bS + brow * ROWB + bcolb);
                ldsm_x4(bf[2][0], bf[2][1], bf[3][0], bf[3][1],
                        bS + (brow + 16) * ROWB + bcolb);
            }
#pragma unroll
            for (int mt = 0; mt < 4; mt++)
#pragma unroll
                for (int nt = 0; nt < 4; nt++)
                    mma_f16(acc[mt][nt], af[mt], bf[nt]);
        }

        buf = (buf == NST - 1) ? 0 : buf + 1;
    }

    // ---- epilogue ----
#pragma unroll
    for (int mt = 0; mt < 4; mt++) {
#pragma unroll
        for (int half = 0; half < 2; half++) {
            int gm = m0 + wm + mt * 16 + r + half * 8;
            if (gm >= M) continue;
#pragma unroll
            for (int nt = 0; nt < 4; nt++) {
                int gn = n0 + wn + nt * 8 + c * 2;
                float v0 = acc[mt][nt][half * 2 + 0];
                float v1 = acc[mt][nt][half * 2 + 1];
                if (bias) {
                    v0 += bias[gn];
                    v1 += bias[gn + 1];
                }
                if (GELU) {
                    v0 = 0.5f * v0 * (1.f + erff(v0 * 0.70710678118654752f));
                    v1 = 0.5f * v1 * (1.f + erff(v1 * 0.70710678118654752f));
                }
                if (resid) {
                    const float2 rr = *reinterpret_cast<const float2*>(
                        &resid[(size_t)gm * N + gn]);
                    v0 += rr.x;
                    v1 += rr.y;
                }
                if (OUTH) {
                    __half2 hv = __floats2half2_rn(v0, v1);
                    *reinterpret_cast<__half2*>(
                        (__half*)Cout + (size_t)gm * N + gn) = hv;
                } else {
                    *reinterpret_cast<float2*>(
                        (float*)Cout + (size_t)gm * N + gn) = make_float2(v0, v1);
                }
            }
        }
    }
}

// ---------------- weight preprocessing ----------------------------------------
__global__ void half_kernel(const float* __restrict__ src, __half* __restrict__ dst,
                            int n4) {
    int i = blockIdx.x * blockDim.x + threadIdx.x;
    if (i >= n4) return;
    float4 v = reinterpret_cast<const float4*>(src)[i];
    __half2 h0 = __floats2half2_rn(v.x, v.y);
    __half2 h1 = __floats2half2_rn(v.z, v.w);
    reinterpret_cast<__half2*>(dst)[2 * i + 0] = h0;
    reinterpret_cast<__half2*>(dst)[2 * i + 1] = h1;
}

// (K,N) fp32 row-major -> (N,K) fp16 row-major; layer via blockIdx.z
__global__ void __launch_bounds__(256)
transpose_half_kernel(const float* __restrict__ src, __half* __restrict__ dst,
                      int K, int N) {
    __shared__ float tile[32][33];
    const float* s = src + (size_t)blockIdx.z * K * N;
    __half* d = dst + (size_t)blockIdx.z * K * N;
    int kb = blockIdx.y * 32, nb = blockIdx.x * 32;
    int tx = threadIdx.x & 31, ty = threadIdx.x >> 5;
#pragma unroll
    for (int r = 0; r < 32; r += 8)
        tile[ty + r][tx] = s[(size_t)(kb + ty + r) * N + nb + tx];
    __syncthreads();
#pragma unroll
    for (int r = 0; r < 32; r += 8)
        d[(size_t)(nb + ty + r) * K + kb + tx] = __float2half(tile[tx][ty + r]);
}

// ---------------- small SIMT GEMM (head: M=32, N=1000) ------------------------
#define BN 128

__global__ void __launch_bounds__(256)
gemm_small(int M, int N, int K,
           const float* __restrict__ A, const float* __restrict__ B,
           const float* __restrict__ bias, float* __restrict__ C) {
    __shared__ float As[8][128];
    __shared__ float Bs[8][132];
    const int tid = threadIdx.x;
    const int m0 = blockIdx.y * 128;
    const int n0 = blockIdx.x * BN;
    const int tx = tid % 16;
    const int ty = tid / 16;

    float acc[8][8];
#pragma unroll
    for (int i = 0; i < 8; i++)
#pragma unroll
        for (int j = 0; j < 8; j++) acc[i][j] = 0.f;

    const int arow = tid / 2;
    const int acol = (tid % 2) * 4;
    const int brow = tid / 32;
    const int bcol = (tid % 32) * 4;

    for (int k0 = 0; k0 < K; k0 += 8) {
        {
            int gm = m0 + arow;
            float4 v = make_float4(0.f, 0.f, 0.f, 0.f);
            if (gm < M)
                v = *reinterpret_cast<const float4*>(&A[(size_t)gm * K + k0 + acol]);
            As[acol + 0][arow] = v.x;
            As[acol + 1][arow] = v.y;
            As[acol + 2][arow] = v.z;
            As[acol + 3][arow] = v.w;
        }
        {
            int gn = n0 + bcol;
            Bs[brow][bcol + 0] = (gn + 0 < N) ? B[(size_t)(k0 + brow) * N + gn + 0] : 0.f;
            Bs[brow][bcol + 1] = (gn + 1 < N) ? B[(size_t)(k0 + brow) * N + gn + 1] : 0.f;
            Bs[brow][bcol + 2] = (gn + 2 < N) ? B[(size_t)(k0 + brow) * N + gn + 2] : 0.f;
            Bs[brow][bcol + 3] = (gn + 3 < N) ? B[(size_t)(k0 + brow) * N + gn + 3] : 0.f;
        }
        __syncthreads();
#pragma unroll
        for (int kk = 0; kk < 8; kk++) {
            float ra[8], rb[8];
#pragma unroll
            for (int i = 0; i < 8; i++) ra[i] = As[kk][ty * 8 + i];
#pragma unroll
            for (int j = 0; j < 8; j++) rb[j] = Bs[kk][tx * 8 + j];
#pragma unroll
            for (int i = 0; i < 8; i++)
#pragma unroll
                for (int j = 0; j < 8; j++) acc[i][j] = fmaf(ra[i], rb[j], acc[i][j]);
        }
        __syncthreads();
    }
#pragma unroll
    for (int i = 0; i < 8; i++) {
        int gm = m0 + ty * 8 + i;
        if (gm >= M) continue;
#pragma unroll
        for (int j = 0; j < 8; j++) {
            int gn = n0 + tx * 8 + j;
            if (gn >= N) continue;
            float v = acc[i][j];
            if (bias) v += bias[gn];
            C[(size_t)gm * N + gn] = v;
        }
    }
}

// ---------------- patch gather (fp16 output) ----------------------------------
__global__ void gather_kernel(const float* __restrict__ x) {
    int idx = blockIdx.x * blockDim.x + threadIdx.x;
    const int total = BATCH * NPATCH * CDIM;
    if (idx >= total) return;
    int k = idx % CDIM;
    int g = (idx / CDIM) % NPATCH;
    int b = idx / (CDIM * NPATCH);
    int ch = k / (PSZ * PSZ);
    int pr = (k / PSZ) % PSZ;
    int pc = k % PSZ;
    int gr = g / GRD;
    int gc = g % GRD;
    g_xp16[idx] = __float2half(
        x[(((size_t)b * 3 + ch) * IMG + gr * PSZ + pr) * IMG + gc * PSZ + pc]);
}

// ---------------- assemble t = [cls; patches] + pos --------------------------
__global__ void assemble_kernel(const float* __restrict__ cls_tok,
                                const float* __restrict__ pos) {
    int idx = blockIdx.x * blockDim.x + threadIdx.x;
    const int total = BATCH * NTOK * CDIM;
    if (idx >= total) return;
    int c = idx % CDIM;
    int n = (idx / CDIM) % NTOK;
    int b = idx / (CDIM * NTOK);
    float v = (n == 0) ? cls_tok[c] : g_h[((size_t)b * NPATCH + n - 1) * CDIM + c];
    g_t[idx] = v + pos[(size_t)n * CDIM + c];
}

// ---------------- layernorm: warp-per-row, barrier-free, float4 ---------------
__global__ void __launch_bounds__(256)
ln_kernel(const float* __restrict__ x, long in_stride,
          const float* __restrict__ w, const float* __restrict__ b,
          void* __restrict__ y, long out_stride, int half_out, int nrows) {
    const int row = (blockIdx.x << 3) + (threadIdx.x >> 5);
    const int lane = threadIdx.x & 31;
    if (row >= nrows) return;
    const float* rp = x + (size_t)row * in_stride;

    float4 v[6];
    float s = 0.f, s2 = 0.f;
#pragma unroll
    for (int i = 0; i < 6; i++) {
        v[i] = *reinterpret_cast<const float4*>(rp + (i * 32 + lane) * 4);
        s += v[i].x + v[i].y + v[i].z + v[i].w;
        s2 += v[i].x * v[i].x + v[i].y * v[i].y + v[i].z * v[i].z + v[i].w * v[i].w;
    }
#pragma unroll
    for (int o = 16; o > 0; o >>= 1) {
        s += __shfl_xor_sync(0xffffffffu, s, o);
        s2 += __shfl_xor_sync(0xffffffffu, s2, o);
    }
    float mu = s * (1.f / CDIM);
    float var = s2 * (1.f / CDIM) - mu * mu;
    float rstd = rsqrtf(var + 1e-5f);

#pragma unroll
    for (int i = 0; i < 6; i++) {
        int c4 = (i * 32 + lane) * 4;
        float4 wv = *reinterpret_cast<const float4*>(w + c4);
        float4 bv = *reinterpret_cast<const float4*>(b + c4);
        float o0 = (v[i].x - mu) * rstd * wv.x + bv.x;
        float o1 = (v[i].y - mu) * rstd * wv.y + bv.y;
        float o2 = (v[i].z - mu) * rstd * wv.z + bv.z;
        float o3 = (v[i].w - mu) * rstd * wv.w + bv.w;
        if (half_out) {
            __half2 h0 = __floats2half2_rn(o0, o1);
            __half2 h1 = __floats2half2_rn(o2, o3);
            uint2 pk;
            pk.x = *reinterpret_cast<uint32_t*>(&h0);
            pk.y = *reinterpret_cast<uint32_t*>(&h1);
            *reinterpret_cast<uint2*>((__half*)y + (size_t)row * out_stride + c4) = pk;
        } else {
            *reinterpret_cast<float4*>((float*)y + (size_t)row * out_stride + c4) =
                make_float4(o0, o1, o2, o3);
        }
    }
}

// ---------------- fused flash attention (fp16 qkv in, float4 smem) ------------
#define FBQ 32
#define FBK 32
#define FPAD 4

__device__ __forceinline__ bool attn_allowed(int q, int k) {
    if (q == 0 || k == 0) return true;
    int qr = (q - 1) / GRD, qc = (q - 1) % GRD;
    int kr = (k - 1) / GRD, kc = (k - 1) % GRD;
    return (abs(qr - kr) <= HALFW) && (abs(qc - kc) <= HALFW);
}

__device__ __forceinline__ void h8_to_smem(const uint4& raw, float* dst) {
    const __half2* hp = reinterpret_cast<const __half2*>(&raw);
    float2 f0 = __half22float2(hp[0]);
    float2 f1 = __half22float2(hp[1]);
    float2 f2 = __half22float2(hp[2]);
    float2 f3 = __half22float2(hp[3]);
    *reinterpret_cast<float4*>(dst) = make_float4(f0.x, f0.y, f1.x, f1.y);
    *reinterpret_cast<float4*>(dst + 4) = make_float4(f2.x, f2.y, f3.x, f3.y);
}

__global__ void __launch_bounds__(256)
flash_kernel() {
    const int b = blockIdx.z;
    const int h = blockIdx.y;
    const int q0 = blockIdx.x * FBQ;
    const int tid = threadIdx.x;

    __shared__ float Qs[FBQ][HD + FPAD];
    __shared__ float Ks[FBK][HD + FPAD];
    __shared__ float Vs[FBK][HD + FPAD];
    __shared__ float Ps[FBQ][FBK + 1];

    const __half* qkv = g_qkv16;
    const size_t rowstride = 3 * CDIM;

    {
        int idx = tid;
        int q = idx >> 3, d8 = (idx & 7) * 8;
        int gq = q0 + q;
        uint4 raw = make_uint4(0u, 0u, 0u, 0u);
        if (gq < NTOK)
            raw = *reinterpret_cast<const uint4*>(
                &qkv[((size_t)(b * NTOK + gq)) * rowstride + h * HD + d8]);
        h8_to_smem(raw, &Qs[q][d8]);
    }

    int klo = 0, khi = NTOK - 1;
    bool full = (q0 == 0);
    if (!full) {
        int qlo = q0, qhi = min(q0 + FBQ - 1, NTOK - 1);
        int qr_min = (qlo - 1) / GRD, qr_max = (qhi - 1) / GRD;
        klo = 1 + max(0, qr_min - HALFW) * GRD;
        khi = min(NTOK - 1, (qr_max + HALFW) * GRD + GRD);
    }

    const int q = tid >> 3;
    const int j = tid & 7;
    const int gq = q0 + q;
    const bool qvalid = (gq < NTOK);
    const int dbase = j * 8;

    float m_old = -INFINITY, l = 0.f;
    float acc[8];
#pragma unroll
    for (int i = 0; i < 8; i++) acc[i] = 0.f;

    for (int kt = 0; kt < (NTOK + FBK - 1) / FBK; kt++) {
        int kbase = kt * FBK;
        if (!(kt == 0 || full || (kbase + FBK - 1 >= klo && kbase <= khi)))
            continue;

        __syncthreads();
        {
            int idx = tid;
            int kk = idx >> 3, d8 = (idx & 7) * 8;
            int gk = kbase + kk;
            uint4 kraw = make_uint4(0u, 0u, 0u, 0u);
            uint4 vraw = make_uint4(0u, 0u, 0u, 0u);
            if (gk < NTOK) {
                kraw = *reinterpret_cast<const uint4*>(
                    &qkv[((size_t)(b * NTOK + gk)) * rowstride + CDIM + h * HD + d8]);
                vraw = *reinterpret_cast<const uint4*>(
                    &qkv[((size_t)(b * NTOK + gk)) * rowstride + 2 * CDIM + h * HD + d8]);
            }
            h8_to_smem(kraw, &Ks[kk][d8]);
            h8_to_smem(vraw, &Vs[kk][d8]);
        }
        __syncthreads();

        float s[4] = {0.f, 0.f, 0.f, 0.f};
#pragma unroll
        for (int d4 = 0; d4 < HD; d4 += 4) {
            float4 qv = *reinterpret_cast<const float4*>(&Qs[q][d4]);
#pragma unroll
            for (int i = 0; i < 4; i++) {
                float4 kv = *reinterpret_cast<const float4*>(&Ks[j + i * 8][d4]);
                s[i] = fmaf(qv.x, kv.x, s[i]);
                s[i] = fmaf(qv.y, kv.y, s[i]);
                s[i] = fmaf(qv.z, kv.z, s[i]);
                s[i] = fmaf(qv.w, kv.w, s[i]);
            }
        }
#pragma unroll
        for (int i = 0; i < 4; i++) {
            float a = s[i] * 0.125f;
            int gk = kbase + j + i * 8;
            if (!qvalid || gk >= NTOK || !attn_allowed(gq, gk)) a = -INFINITY;
            s[i] = a;
        }
        float mt = fmaxf(fmaxf(s[0], s[1]), fmaxf(s[2], s[3]));
#pragma unroll
        for (int o = 1; o < 8; o <<= 1)
            mt = fmaxf(mt, __shfl_xor_sync(0xffffffffu, mt, o));
        float m_new = fmaxf(m_old, mt);
        float scale = (m_new == -INFINITY) ? 1.f : __expf(m_old - m_new);
        float psum = 0.f;
#pragma unroll
        for (int i = 0; i < 4; i++) {
            float p = (s[i] == -INFINITY) ? 0.f : __expf(s[i] - m_new);
            Ps[q][j + i * 8] = p;
            psum += p;
        }
#pragma unroll
        for (int o = 1; o < 8; o <<= 1)
            psum += __shfl_xor_sync(0xffffffffu, psum, o);
        l = l * scale + psum;
        m_old = m_new;
        __syncwarp();

#pragma unroll
        for (int i = 0; i < 8; i++) acc[i] *= scale;
        for (int kk = 0; kk < FBK; kk++) {
            float p = Ps[q][kk];
            float4 v0 = *reinterpret_cast<const float4*>(&Vs[kk][dbase]);
            float4 v1 = *reinterpret_cast<const float4*>(&Vs[kk][dbase + 4]);
            acc[0] = fmaf(p, v0.x, acc[0]);
            acc[1] = fmaf(p, v0.y, acc[1]);
            acc[2] = fmaf(p, v0.z, acc[2]);
            acc[3] = fmaf(p, v0.w, acc[3]);
            acc[4] = fmaf(p, v1.x, acc[4]);
            acc[5] = fmaf(p, v1.y, acc[5]);
            acc[6] = fmaf(p, v1.z, acc[6]);
            acc[7] = fmaf(p, v1.w, acc[7]);
        }
        __syncwarp();
    }

    if (qvalid) {
        float inv = 1.f / l;
        __half2 hv[4];
#pragma unroll
        for (int i = 0; i < 4; i++)
            hv[i] = __floats2half2_rn(acc[2 * i] * inv, acc[2 * i + 1] * inv);
        *reinterpret_cast<uint2*>(
            &g_o16[((size_t)(b * NTOK + gq)) * CDIM + h * HD + dbase]) =
            *reinterpret_cast<uint2*>(&hv[0]);
        *reinterpret_cast<uint2*>(
            &g_o16[((size_t)(b * NTOK + gq)) * CDIM + h * HD + dbase + 4]) =
            *reinterpret_cast<uint2*>(&hv[2]);
    }
}

// ---------------- launch helpers ---------------------------------------------
static inline dim3 gh_grid(int M, int N) {
    return dim3(N / GN, (M + GM - 1) / GM);
}

extern "C" void kernel_launch(void* const* d_in, const int* in_sizes, int n_in,
                              void* d_out, int out_size) {
    const float* x       = (const float*)d_in[0];
    const float* patch_w = (const float*)d_in[1];
    const float* patch_b = (const float*)d_in[2];
    const float* cls_tok = (const float*)d_in[3];
    const float* pos     = (const float*)d_in[4];
    const float* ln1_w   = (const float*)d_in[5];
    const float* ln1_b   = (const float*)d_in[6];
    const float* qkv_w   = (const float*)d_in[7];
    const float* proj_w  = (const float*)d_in[8];
    const float* proj_b  = (const float*)d_in[9];
    const float* ln2_w   = (const float*)d_in[10];
    const float* ln2_b   = (const float*)d_in[11];
    const float* mlp_w1  = (const float*)d_in[12];
    const float* mlp_b1  = (const float*)d_in[13];
    const float* mlp_w2  = (const float*)d_in[14];
    const float* mlp_b2  = (const float*)d_in[15];
    const float* norm_w  = (const float*)d_in[16];
    const float* norm_b  = (const float*)d_in[17];
    const float* head_w  = (const float*)d_in[18];
    const float* head_b  = (const float*)d_in[19];
    float* out = (float*)d_out;

    float *t, *h, *cls;
    __half *xp16, *h16, *o16, *mlp16, *qkv16, *w16;
    cudaGetSymbolAddress((void**)&t, g_t);
    cudaGetSymbolAddress((void**)&h, g_h);
    cudaGetSymbolAddress((void**)&cls, g_cls);
    cudaGetSymbolAddress((void**)&xp16, g_xp16);
    cudaGetSymbolAddress((void**)&h16, g_h16);
    cudaGetSymbolAddress((void**)&o16, g_o16);
    cudaGetSymbolAddress((void**)&mlp16, g_mlp16);
    cudaGetSymbolAddress((void**)&qkv16, g_qkv16);
    cudaGetSymbolAddress((void**)&w16, g_w16);

    cudaFuncSetAttribute(gemm_h<false, false>,
                         cudaFuncAttributeMaxDynamicSharedMemorySize, GSMEM);
    cudaFuncSetAttribute(gemm_h<false, true>,
                         cudaFuncAttributeMaxDynamicSharedMemorySize, GSMEM);
    cudaFuncSetAttribute(gemm_h<true, true>,
                         cudaFuncAttributeMaxDynamicSharedMemorySize, GSMEM);

    const __half* w_patch = w16 + OFF_PATCH;
    const __half* w_qkv   = w16 + OFF_QKV;
    const __half* w_proj  = w16 + OFF_PROJ;
    const __half* w_mlp1  = w16 + OFF_MLP1;
    const __half* w_mlp2  = w16 + OFF_MLP2;

    // ---- preprocess weights: (N,K) fp16 ----
    half_kernel<<<(W_PATCH_SZ / 4 + 255) / 256, 256>>>(
        patch_w, w16 + OFF_PATCH, W_PATCH_SZ / 4);  // already (N,K)
    transpose_half_kernel<<<dim3(3 * CDIM / 32, CDIM / 32, DEPTH), 256>>>(
        qkv_w, w16 + OFF_QKV, CDIM, 3 * CDIM);
    transpose_half_kernel<<<dim3(CDIM / 32, CDIM / 32, DEPTH), 256>>>(
        proj_w, w16 + OFF_PROJ, CDIM, CDIM);
    transpose_half_kernel<<<dim3(HIDDIM / 32, CDIM / 32, DEPTH), 256>>>(
        mlp_w1, w16 + OFF_MLP1, CDIM, HIDDIM);
    transpose_half_kernel<<<dim3(CDIM / 32, HIDDIM / 32, DEPTH), 256>>>(
        mlp_w2, w16 + OFF_MLP2, HIDDIM, CDIM);

    const int Mtok = BATCH * NTOK;  // 6304
    const int lnBlocks = (Mtok + 7) / 8;

    // patch embed
    {
        int total = BATCH * NPATCH * CDIM;
        gather_kernel<<<(total + 255) / 256, 256>>>(x);
        gemm_h<false, false><<<gh_grid(BATCH * NPATCH, CDIM), 256, GSMEM>>>(
            BATCH * NPATCH, CDIM, CDIM, xp16, w_patch, patch_b, nullptr, h);
        int tot2 = BATCH * NTOK * CDIM;
        assemble_kernel<<<(tot2 + 255) / 256, 256>>>(cls_tok, pos);
    }

    for (int i = 0; i < DEPTH; i++) {
        ln_kernel<<<lnBlocks, 256>>>(t, CDIM, ln1_w + i * CDIM, ln1_b + i * CDIM,
                                     h16, CDIM, 1, Mtok);
        gemm_h<false, true><<<gh_grid(Mtok, 3 * CDIM), 256, GSMEM>>>(
            Mtok, 3 * CDIM, CDIM, h16, w_qkv + (size_t)i * CDIM * 3 * CDIM,
            nullptr, nullptr, qkv16);
        flash_kernel<<<dim3((NTOK + FBQ - 1) / FBQ, NHEADS, BATCH), 256>>>();
        gemm_h<false, false><<<gh_grid(Mtok, CDIM), 256, GSMEM>>>(
            Mtok, CDIM, CDIM, o16, w_proj + (size_t)i * CDIM * CDIM,
            proj_b + i * CDIM, t, t);
        ln_kernel<<<lnBlocks, 256>>>(t, CDIM, ln2_w + i * CDIM, ln2_b + i * CDIM,
                                     h16, CDIM, 1, Mtok);
        gemm_h<true, true><<<gh_grid(Mtok, HIDDIM), 256, GSMEM>>>(
            Mtok, HIDDIM, CDIM, h16, w_mlp1 + (size_t)i * CDIM * HIDDIM,
            mlp_b1 + i * HIDDIM, nullptr, mlp16);
        gemm_h<false, false><<<gh_grid(Mtok, CDIM), 256, GSMEM>>>(
            Mtok, CDIM, HIDDIM, mlp16, w_mlp2 + (size_t)i * HIDDIM * CDIM,
            mlp_b2 + i * CDIM, t, t);
    }

    ln_kernel<<<(BATCH + 7) / 8, 256>>>(t, (long)NTOK * CDIM, norm_w, norm_b,
                                        cls, CDIM, 0, BATCH);
    gemm_small<<<dim3((NCLS + BN - 1) / BN, 1), 256>>>(
        BATCH, NCLS, CDIM, cls, head_w, head_b, out);
}